// round 3
// baseline (speedup 1.0000x reference)
#include <cuda_runtime.h>
#include <cstdint>
#include <cstddef>

// ---------------- problem constants ----------------
#define NUM_HEADS 8
#define DHEAD 32
#define BLOCK_SZ 8
#define HALO 3
#define WIN 14          // BLOCK + 2*HALO
#define WINP 196        // WIN*WIN
#define NHB 12          // 96/8
#define NB 144          // 12*12
#define HW 96
#define SPATIAL 9216    // 96*96
#define BATCH 8
#define CIN 256
#define OQKV 768        // 256 q + 512 kv
#define SCALE 0.17677669529663687f

typedef unsigned long long u64;

// ---- f32x2 packed-math helpers (Blackwell dual-rate fp32) ----
__device__ __forceinline__ u64 pack2(float lo, float hi) {
    u64 r; asm("mov.b64 %0, {%1, %2};" : "=l"(r) : "f"(lo), "f"(hi)); return r;
}
__device__ __forceinline__ void unpack2(u64 v, float& lo, float& hi) {
    asm("mov.b64 {%0, %1}, %2;" : "=f"(lo), "=f"(hi) : "l"(v));
}
__device__ __forceinline__ void fma2(u64& d, u64 a, u64 b) {
    asm("fma.rn.f32x2 %0, %1, %2, %0;" : "+l"(d) : "l"(a), "l"(b));
}
__device__ __forceinline__ void mul2(u64& d, u64 a) {
    asm("mul.rn.f32x2 %0, %0, %1;" : "+l"(d) : "l"(a));
}
__device__ __forceinline__ u64 add2(u64 a, u64 b) {
    u64 r; asm("add.rn.f32x2 %0, %1, %2;" : "=l"(r) : "l"(a), "l"(b)); return r;
}

// scratch: qkv[b][o][s], o<256 -> q (head*32+d), o>=256 -> kv (256 + head*64 + c)
__device__ float g_qkv[(size_t)BATCH * OQKV * SPATIAL];

// ---------------- kernel 1: fused QKV projection GEMM ----------------
// C[b][o][s] = sum_c W[o][c] * x[b][c][s]
// tile 128x128, BK=16, 256 threads, 8x8 micro-tile, FFMA2 inner product.
// B is stored DUPLICATED in smem so bd pairs load directly (no mov.b64 packs).
#define GBM 128
#define GBN 128
#define GBK 16
#define APAD 132   // As row stride (words)

__global__ void __launch_bounds__(256, 2) qkv_gemm(
    const float* __restrict__ x,
    const float* __restrict__ qw,
    const float* __restrict__ kvw)
{
    __shared__ float As[GBK][APAD];       // [k][m]
    __shared__ float Bs[GBK][2 * GBN];    // [k][2n] duplicated: {b,b}

    const int b  = blockIdx.z;
    const int m0 = blockIdx.y * GBM;
    const int n0 = blockIdx.x * GBN;
    const int tid = threadIdx.x;

    const float* xb = x + (size_t)b * CIN * SPATIAL;

    const int tr = tid >> 4;          // 0..15 : rows tr*8 .. +7
    const int tc = tid & 15;          // 0..15 : cols tc*8 .. +7

    const int a_row0 = tid >> 2;
    const int a_ck   = (tid & 3) * 4;
    const int b_kr0  = tid >> 5;
    const int b_col  = (tid & 31) * 4;

    const float* wrowp[2];
#pragma unroll
    for (int i = 0; i < 2; i++) {
        const int o = m0 + a_row0 + i * 64;
        wrowp[i] = (o < 256) ? (qw + (size_t)o * CIN) : (kvw + (size_t)(o - 256) * CIN);
    }

    u64 acc2[4][8];
#pragma unroll
    for (int i = 0; i < 4; i++)
#pragma unroll
        for (int j = 0; j < 8; j++) acc2[i][j] = 0ULL;

    float4 pa[2], pb[2];
#pragma unroll
    for (int i = 0; i < 2; i++) {
        pa[i] = *(const float4*)(wrowp[i] + 0 + a_ck);
        pb[i] = *(const float4*)(xb + (size_t)(0 + b_kr0 + i * 8) * SPATIAL + n0 + b_col);
    }

    for (int k0 = 0; k0 < CIN; k0 += GBK) {
#pragma unroll
        for (int i = 0; i < 2; i++) {
            const int ar = a_row0 + i * 64;
            As[a_ck + 0][ar] = pa[i].x;
            As[a_ck + 1][ar] = pa[i].y;
            As[a_ck + 2][ar] = pa[i].z;
            As[a_ck + 3][ar] = pa[i].w;
            float* brow = &Bs[b_kr0 + i * 8][2 * b_col];
            *(float2*)(brow + 0) = make_float2(pb[i].x, pb[i].x);
            *(float2*)(brow + 2) = make_float2(pb[i].y, pb[i].y);
            *(float2*)(brow + 4) = make_float2(pb[i].z, pb[i].z);
            *(float2*)(brow + 6) = make_float2(pb[i].w, pb[i].w);
        }
        __syncthreads();

        if (k0 + GBK < CIN) {
#pragma unroll
            for (int i = 0; i < 2; i++) {
                pa[i] = *(const float4*)(wrowp[i] + k0 + GBK + a_ck);
                pb[i] = *(const float4*)(xb + (size_t)(k0 + GBK + b_kr0 + i * 8) * SPATIAL + n0 + b_col);
            }
        }

#pragma unroll
        for (int k = 0; k < GBK; k++) {
            ulonglong2 a01 = *(const ulonglong2*)&As[k][tr * 8];
            ulonglong2 a23 = *(const ulonglong2*)&As[k][tr * 8 + 4];
            u64 a2[4] = {a01.x, a01.y, a23.x, a23.y};
            const ulonglong2* bp = (const ulonglong2*)&Bs[k][2 * (tc * 8)];
            ulonglong2 b01 = bp[0];
            ulonglong2 b23 = bp[1];
            ulonglong2 b45 = bp[2];
            ulonglong2 b67 = bp[3];
            u64 bd[8] = {b01.x, b01.y, b23.x, b23.y, b45.x, b45.y, b67.x, b67.y};
#pragma unroll
            for (int i = 0; i < 4; i++)
#pragma unroll
                for (int j = 0; j < 8; j++)
                    fma2(acc2[i][j], a2[i], bd[j]);
        }
        __syncthreads();
    }

    float* outb = g_qkv + (size_t)b * OQKV * SPATIAL;
#pragma unroll
    for (int i = 0; i < 4; i++) {
        float lo[8], hi[8];
#pragma unroll
        for (int j = 0; j < 8; j++) unpack2(acc2[i][j], lo[j], hi[j]);
        const int r0 = m0 + tr * 8 + 2 * i;
        float* p0 = outb + (size_t)r0 * SPATIAL + n0 + tc * 8;
        float* p1 = p0 + SPATIAL;
        *(float4*)(p0)     = make_float4(lo[0], lo[1], lo[2], lo[3]);
        *(float4*)(p0 + 4) = make_float4(lo[4], lo[5], lo[6], lo[7]);
        *(float4*)(p1)     = make_float4(hi[0], hi[1], hi[2], hi[3]);
        *(float4*)(p1 + 4) = make_float4(hi[4], hi[5], hi[6], hi[7]);
    }
}

// ---------------- kernel 2: halo attention ----------------
// grid (144, 64), 128 threads, 3 blocks/SM target.
// thread t: qp = t>>2 (queries qp and qp+32), quad = t&3 -> 7x7 quadrant.
// Rel-position per-thread terms live in smem (register relief).
#define KV_STRIDE 68                         // 64 ch + pad
#define SMEM_KV   (WINP * KV_STRIDE)         // 13328 floats
#define RELSTRIDE 36
#define SMEM_REL  (27 * RELSTRIDE)           // 972 floats each
#define PTSTRIDE  29                         // per-thread rel stash stride
#define SMEM_PT   (128 * PTSTRIDE)           // 3712 floats
#define SMEM_FLOATS (SMEM_KV + 2 * SMEM_REL + SMEM_PT)
#define SMEM_BYTES  (SMEM_FLOATS * 4)

__global__ void __launch_bounds__(128, 3) halo_attn(
    const float* __restrict__ hrel,
    const float* __restrict__ wrel,
    float* __restrict__ out)
{
    extern __shared__ float smem[];
    float* sKV = smem;                       // [196][68] : c<32 K, c>=32 V
    float* sH  = smem + SMEM_KV;             // [27][36]
    float* sW  = sH + SMEM_REL;              // [27][36]
    float* sPT = sW + SMEM_REL;              // [128][29]: rwA[7] rwB[7] rhA[7] rhB[7]

    const int tid = threadIdx.x;
    const int nbidx = blockIdx.x;            // 0..143
    const int bh = blockIdx.y;               // 0..63
    const int b = bh >> 3, head = bh & 7;
    const int by = nbidx / NHB, bx = nbidx % NHB;

    // ---- stage rel tables ----
    for (int idx = tid; idx < 27 * 32; idx += 128) {
        const int r = idx >> 5, d = idx & 31;
        sH[r * RELSTRIDE + d] = hrel[idx];
        sW[r * RELSTRIDE + d] = wrel[idx];
    }

    // ---- stage KV window (global c-major -> shared pos-major) ----
    const float* kvbase = g_qkv + ((size_t)b * OQKV + 256 + head * 64) * SPATIAL;
    for (int idx = tid; idx < 64 * WINP; idx += 128) {
        const int c = idx / WINP, p = idx % WINP;
        const int y = p / WIN, xx = p % WIN;
        const int gh = by * BLOCK_SZ + y - HALO;
        const int gw = bx * BLOCK_SZ + xx - HALO;
        float v = 0.f;
        if ((unsigned)gh < (unsigned)HW && (unsigned)gw < (unsigned)HW)
            v = kvbase[(size_t)c * SPATIAL + gh * HW + gw];
        sKV[p * KV_STRIDE + c] = v;
    }

    // ---- per-thread work assignment ----
    const int qp   = tid >> 2;               // 0..31
    const int quad = tid & 3;
    const int y0 = (quad >> 1) * 7;
    const int x0 = (quad & 1) * 7;

    const int qiA = qp >> 3;                  // 0..3
    const int qj  = qp & 7;
    const int qiB = qiA + 4;

    const int spA = (by * BLOCK_SZ + qiA) * HW + bx * BLOCK_SZ + qj;
    const int spB = (by * BLOCK_SZ + qiB) * HW + bx * BLOCK_SZ + qj;

    // ---- load both Q rows as f32x2 d-pairs ----
    const float* qbA = g_qkv + ((size_t)b * OQKV + head * DHEAD) * SPATIAL + spA;
    const float* qbB = qbA + (spB - spA);

    u64 qa2[16], qb2[16];
#pragma unroll
    for (int dd = 0; dd < 16; dd++) {
        qa2[dd] = pack2(qbA[(size_t)(2 * dd) * SPATIAL], qbA[(size_t)(2 * dd + 1) * SPATIAL]);
        qb2[dd] = pack2(qbB[(size_t)(2 * dd) * SPATIAL], qbB[(size_t)(2 * dd + 1) * SPATIAL]);
    }

    __syncthreads();

    // ---- relative-position terms -> per-thread smem stash ----
    float* myPT = &sPT[tid * PTSTRIDE];
#pragma unroll
    for (int i = 0; i < 7; i++) {
        {   // width rel, row 13 + (x0+i) - qj
            const ulonglong2* wr = (const ulonglong2*)&sW[(13 + x0 + i - qj) * RELSTRIDE];
            u64 s0 = 0ULL, s1 = 0ULL, t0 = 0ULL, t1 = 0ULL;
#pragma unroll
            for (int m = 0; m < 8; m++) {
                ulonglong2 wv = wr[m];
                fma2(s0, qa2[2 * m],     wv.x);
                fma2(s1, qa2[2 * m + 1], wv.y);
                fma2(t0, qb2[2 * m],     wv.x);
                fma2(t1, qb2[2 * m + 1], wv.y);
            }
            float l0, h0;
            unpack2(add2(s0, s1), l0, h0);
            myPT[i] = l0 + h0;            // rwA
            unpack2(add2(t0, t1), l0, h0);
            myPT[7 + i] = l0 + h0;        // rwB
        }
        {   // height rel
            const ulonglong2* hrA = (const ulonglong2*)&sH[(13 + y0 + i - qiA) * RELSTRIDE];
            const ulonglong2* hrB = (const ulonglong2*)&sH[(13 + y0 + i - qiB) * RELSTRIDE];
            u64 s0 = 0ULL, s1 = 0ULL, t0 = 0ULL, t1 = 0ULL;
#pragma unroll
            for (int m = 0; m < 8; m++) {
                ulonglong2 hvA = hrA[m];
                ulonglong2 hvB = hrB[m];
                fma2(s0, qa2[2 * m],     hvA.x);
                fma2(s1, qa2[2 * m + 1], hvA.y);
                fma2(t0, qb2[2 * m],     hvB.x);
                fma2(t1, qb2[2 * m + 1], hvB.y);
            }
            float l0, h0;
            unpack2(add2(s0, s1), l0, h0);
            myPT[14 + i] = l0 + h0;       // rhA
            unpack2(add2(t0, t1), l0, h0);
            myPT[21 + i] = l0 + h0;       // rhB
        }
    }

    // fold QK scale into q
    const u64 sc2 = pack2(SCALE, SCALE);
#pragma unroll
    for (int dd = 0; dd < 16; dd++) { mul2(qa2[dd], sc2); mul2(qb2[dd], sc2); }

    // ---- flash loop over the 7x7 quadrant ----
    float mA = -1e30f, lA = 0.f, mB = -1e30f, lB = 0.f;
    u64 accA[16], accB[16];
#pragma unroll
    for (int dd = 0; dd < 16; dd++) { accA[dd] = 0ULL; accB[dd] = 0ULL; }

    for (int yy = 0; yy < 7; yy++) {
        const int prow = (y0 + yy) * WIN + x0;
        const float rhvA = myPT[14 + yy], rhvB = myPT[21 + yy];
        float lgA[7], lgB[7];
        float rmA = -1e30f, rmB = -1e30f;
#pragma unroll
        for (int xx = 0; xx < 7; xx++) {
            const ulonglong2* kp = (const ulonglong2*)(sKV + (prow + xx) * KV_STRIDE);
            u64 sA0 = 0ULL, sA1 = 0ULL, sB0 = 0ULL, sB1 = 0ULL;
#pragma unroll
            for (int m = 0; m < 8; m++) {
                ulonglong2 kv = kp[m];
                fma2(sA0, qa2[2 * m],     kv.x);
                fma2(sA1, qa2[2 * m + 1], kv.y);
                fma2(sB0, qb2[2 * m],     kv.x);
                fma2(sB1, qb2[2 * m + 1], kv.y);
            }
            float l0, h0;
            unpack2(add2(sA0, sA1), l0, h0);
            const float sA = l0 + h0 + rhvA + myPT[xx];
            unpack2(add2(sB0, sB1), l0, h0);
            const float sB = l0 + h0 + rhvB + myPT[7 + xx];
            lgA[xx] = sA; rmA = fmaxf(rmA, sA);
            lgB[xx] = sB; rmB = fmaxf(rmB, sB);
        }
        const float mnA = fmaxf(mA, rmA);
        const float mnB = fmaxf(mB, rmB);
        const float cA = __expf(mA - mnA);
        const float cB = __expf(mB - mnB);
        lA *= cA; lB *= cB;
        const u64 cA2 = pack2(cA, cA), cB2 = pack2(cB, cB);
#pragma unroll
        for (int dd = 0; dd < 16; dd++) { mul2(accA[dd], cA2); mul2(accB[dd], cB2); }
        mA = mnA; mB = mnB;
#pragma unroll
        for (int xx = 0; xx < 7; xx++) {
            const float pA = __expf(lgA[xx] - mA);
            const float pB = __expf(lgB[xx] - mB);
            lA += pA; lB += pB;
            const u64 pA2 = pack2(pA, pA), pB2 = pack2(pB, pB);
            const ulonglong2* vp = (const ulonglong2*)(sKV + (prow + xx) * KV_STRIDE + 32);
#pragma unroll
            for (int m = 0; m < 8; m++) {
                ulonglong2 vv = vp[m];
                fma2(accA[2 * m],     pA2, vv.x);
                fma2(accA[2 * m + 1], pA2, vv.y);
                fma2(accB[2 * m],     pB2, vv.x);
                fma2(accB[2 * m + 1], pB2, vv.y);
            }
        }
    }

    // ---- combine 4 quadrant partials via lane shuffles ----
    const unsigned FULL = 0xFFFFFFFFu;
    float* obA = out + ((size_t)b * 256 + head * DHEAD) * SPATIAL + spA;
    float* obB = obA + (spB - spA);

    {
        float M = mA;
        M = fmaxf(M, __shfl_xor_sync(FULL, M, 1));
        M = fmaxf(M, __shfl_xor_sync(FULL, M, 2));
        const float w = __expf(mA - M);
        float lw = lA * w;
        lw += __shfl_xor_sync(FULL, lw, 1);
        lw += __shfl_xor_sync(FULL, lw, 2);
        const float inv = 1.f / lw;
#pragma unroll
        for (int dd = 0; dd < 16; dd++) {
            float f0, f1; unpack2(accA[dd], f0, f1);
            f0 *= w; f1 *= w;
            f0 += __shfl_xor_sync(FULL, f0, 1);
            f0 += __shfl_xor_sync(FULL, f0, 2);
            f1 += __shfl_xor_sync(FULL, f1, 1);
            f1 += __shfl_xor_sync(FULL, f1, 2);
            if (quad == 0) {
                obA[(size_t)(2 * dd) * SPATIAL]     = f0 * inv;
                obA[(size_t)(2 * dd + 1) * SPATIAL] = f1 * inv;
            }
        }
    }
    {
        float M = mB;
        M = fmaxf(M, __shfl_xor_sync(FULL, M, 1));
        M = fmaxf(M, __shfl_xor_sync(FULL, M, 2));
        const float w = __expf(mB - M);
        float lw = lB * w;
        lw += __shfl_xor_sync(FULL, lw, 1);
        lw += __shfl_xor_sync(FULL, lw, 2);
        const float inv = 1.f / lw;
#pragma unroll
        for (int dd = 0; dd < 16; dd++) {
            float f0, f1; unpack2(accB[dd], f0, f1);
            f0 *= w; f1 *= w;
            f0 += __shfl_xor_sync(FULL, f0, 1);
            f0 += __shfl_xor_sync(FULL, f0, 2);
            f1 += __shfl_xor_sync(FULL, f1, 1);
            f1 += __shfl_xor_sync(FULL, f1, 2);
            if (quad == 0) {
                obB[(size_t)(2 * dd) * SPATIAL]     = f0 * inv;
                obB[(size_t)(2 * dd + 1) * SPATIAL] = f1 * inv;
            }
        }
    }
}

// ---------------- launch ----------------
extern "C" void kernel_launch(void* const* d_in, const int* in_sizes, int n_in,
                              void* d_out, int out_size)
{
    const float* x    = (const float*)d_in[0];
    const float* qw   = (const float*)d_in[1];
    const float* kvw  = (const float*)d_in[2];
    const float* hrel = (const float*)d_in[3];
    const float* wrel = (const float*)d_in[4];
    float* out = (float*)d_out;

    cudaFuncSetAttribute(halo_attn, cudaFuncAttributeMaxDynamicSharedMemorySize,
                         SMEM_BYTES);

    qkv_gemm<<<dim3(SPATIAL / GBN, OQKV / GBM, BATCH), 256>>>(x, qw, kvw);
    halo_attn<<<dim3(NB, BATCH * NUM_HEADS), 128, SMEM_BYTES>>>(hrel, wrel, out);
}

// round 4
// speedup vs baseline: 1.7866x; 1.7866x over previous
#include <cuda_runtime.h>
#include <cstdint>
#include <cstddef>

// ---------------- problem constants ----------------
#define NUM_HEADS 8
#define DHEAD 32
#define BLOCK_SZ 8
#define HALO 3
#define WIN 14          // BLOCK + 2*HALO
#define WINP 196        // WIN*WIN
#define NHB 12          // 96/8
#define NB 144          // 12*12
#define HW 96
#define SPATIAL 9216    // 96*96
#define BATCH 8
#define CIN 256
#define OQKV 768        // 256 q + 512 kv
#define SCALE 0.17677669529663687f

typedef unsigned long long u64;

// ---- f32x2 packed-math helpers (Blackwell dual-rate fp32) ----
__device__ __forceinline__ u64 pack2(float lo, float hi) {
    u64 r; asm("mov.b64 %0, {%1, %2};" : "=l"(r) : "f"(lo), "f"(hi)); return r;
}
__device__ __forceinline__ void unpack2(u64 v, float& lo, float& hi) {
    asm("mov.b64 {%0, %1}, %2;" : "=f"(lo), "=f"(hi) : "l"(v));
}
__device__ __forceinline__ void fma2(u64& d, u64 a, u64 b) {
    asm("fma.rn.f32x2 %0, %1, %2, %0;" : "+l"(d) : "l"(a), "l"(b));
}
__device__ __forceinline__ void mul2(u64& d, u64 a) {
    asm("mul.rn.f32x2 %0, %0, %1;" : "+l"(d) : "l"(a));
}
__device__ __forceinline__ u64 add2(u64 a, u64 b) {
    u64 r; asm("add.rn.f32x2 %0, %1, %2;" : "=l"(r) : "l"(a), "l"(b)); return r;
}

// scratch: qkv[b][o][s], o<256 -> q (head*32+d), o>=256 -> kv (256 + head*64 + c)
__device__ float g_qkv[(size_t)BATCH * OQKV * SPATIAL];

// ---------------- kernel 1: fused QKV projection GEMM ----------------
// C[b][o][s] = sum_c W[o][c] * x[b][c][s]
// tile 128x128, BK=16, 256 threads, 8x8 micro-tile, FFMA2.
// A stored DUPLICATED in smem ({a,a} pairs, broadcast reads -> conflict-free);
// B loaded as natural (b_n, b_{n+1}) pairs. Inner loop has ZERO packs.
#define GBM 128
#define GBN 128
#define GBK 16
#define ADUP 260   // As row stride in words: 2*128 + 4 (1040B = 65*16, aligned)

__global__ void __launch_bounds__(256, 2) qkv_gemm(
    const float* __restrict__ x,
    const float* __restrict__ qw,
    const float* __restrict__ kvw)
{
    __shared__ float As[GBK][ADUP];   // [k][2m] duplicated
    __shared__ float Bs[GBK][GBN];    // [k][n]

    const int b  = blockIdx.z;
    const int m0 = blockIdx.y * GBM;
    const int n0 = blockIdx.x * GBN;
    const int tid = threadIdx.x;

    const float* xb = x + (size_t)b * CIN * SPATIAL;

    const int tr = tid >> 4;          // 0..15 : rows tr*8 .. +7
    const int tc = tid & 15;          // 0..15 : cols tc*8 .. +7

    const int a_row0 = tid >> 2;      // 0..63
    const int a_ck   = (tid & 3) * 4; // 0,4,8,12
    const int b_kr0  = tid >> 5;      // 0..7
    const int b_col  = (tid & 31) * 4;

    const float* wrowp[2];
#pragma unroll
    for (int i = 0; i < 2; i++) {
        const int o = m0 + a_row0 + i * 64;
        wrowp[i] = (o < 256) ? (qw + (size_t)o * CIN) : (kvw + (size_t)(o - 256) * CIN);
    }

    u64 acc2[8][4];   // [m 8][n-pair 4]
#pragma unroll
    for (int i = 0; i < 8; i++)
#pragma unroll
        for (int j = 0; j < 4; j++) acc2[i][j] = 0ULL;

    float4 pa[2], pb[2];
#pragma unroll
    for (int i = 0; i < 2; i++) {
        pa[i] = *(const float4*)(wrowp[i] + 0 + a_ck);
        pb[i] = *(const float4*)(xb + (size_t)(0 + b_kr0 + i * 8) * SPATIAL + n0 + b_col);
    }

    for (int k0 = 0; k0 < CIN; k0 += GBK) {
#pragma unroll
        for (int i = 0; i < 2; i++) {
            const int ar2 = 2 * (a_row0 + i * 64);
            *(float2*)&As[a_ck + 0][ar2] = make_float2(pa[i].x, pa[i].x);
            *(float2*)&As[a_ck + 1][ar2] = make_float2(pa[i].y, pa[i].y);
            *(float2*)&As[a_ck + 2][ar2] = make_float2(pa[i].z, pa[i].z);
            *(float2*)&As[a_ck + 3][ar2] = make_float2(pa[i].w, pa[i].w);
            *(float4*)&Bs[b_kr0 + i * 8][b_col] = pb[i];
        }
        __syncthreads();

        if (k0 + GBK < CIN) {
#pragma unroll
            for (int i = 0; i < 2; i++) {
                pa[i] = *(const float4*)(wrowp[i] + k0 + GBK + a_ck);
                pb[i] = *(const float4*)(xb + (size_t)(k0 + GBK + b_kr0 + i * 8) * SPATIAL + n0 + b_col);
            }
        }

#pragma unroll
        for (int k = 0; k < GBK; k++) {
            const ulonglong2* ap = (const ulonglong2*)&As[k][2 * (tr * 8)];
            ulonglong2 a01 = ap[0], a23 = ap[1], a45 = ap[2], a67 = ap[3];
            u64 ad[8] = {a01.x, a01.y, a23.x, a23.y, a45.x, a45.y, a67.x, a67.y};
            const ulonglong2* bp = (const ulonglong2*)&Bs[k][tc * 8];
            ulonglong2 b01 = bp[0], b23 = bp[1];
            u64 bn[4] = {b01.x, b01.y, b23.x, b23.y};
#pragma unroll
            for (int i = 0; i < 8; i++)
#pragma unroll
                for (int j = 0; j < 4; j++)
                    fma2(acc2[i][j], ad[i], bn[j]);
        }
        __syncthreads();
    }

    float* outb = g_qkv + (size_t)b * OQKV * SPATIAL;
#pragma unroll
    for (int i = 0; i < 8; i++) {
        float lo0, hi0, lo1, hi1, lo2, hi2, lo3, hi3;
        unpack2(acc2[i][0], lo0, hi0);
        unpack2(acc2[i][1], lo1, hi1);
        unpack2(acc2[i][2], lo2, hi2);
        unpack2(acc2[i][3], lo3, hi3);
        float* p = outb + (size_t)(m0 + tr * 8 + i) * SPATIAL + n0 + tc * 8;
        *(float4*)(p)     = make_float4(lo0, hi0, lo1, hi1);
        *(float4*)(p + 4) = make_float4(lo2, hi2, lo3, hi3);
    }
}

// ---------------- kernel 2: halo attention ----------------
// Round-1 structure (1 query/thread, 2-way half split) with f32x2 math.
// grid (144, 64), 128 threads. thread: q = tid>>1, half = tid&1.
#define KV_STRIDE 68                         // 64 ch + pad
#define SMEM_KV   (WINP * KV_STRIDE)         // 13328 floats
#define RELSTRIDE 36                         // 144B rows (16B aligned)
#define SMEM_REL  (27 * RELSTRIDE)           // 972 floats each
#define SMEM_FLOATS (SMEM_KV + 2 * SMEM_REL)
#define SMEM_BYTES  (SMEM_FLOATS * 4)

__global__ void __launch_bounds__(128) halo_attn(
    const float* __restrict__ hrel,
    const float* __restrict__ wrel,
    float* __restrict__ out)
{
    extern __shared__ float smem[];
    float* sKV = smem;                       // [196][68] : c<32 K, c>=32 V
    float* sH  = smem + SMEM_KV;             // [27][36]
    float* sW  = sH + SMEM_REL;              // [27][36]

    const int tid = threadIdx.x;
    const int nbidx = blockIdx.x;            // 0..143
    const int bh = blockIdx.y;               // 0..63
    const int b = bh >> 3, head = bh & 7;
    const int by = nbidx / NHB, bx = nbidx % NHB;

    // ---- stage rel tables ----
    for (int idx = tid; idx < 27 * 32; idx += 128) {
        const int r = idx >> 5, d = idx & 31;
        sH[r * RELSTRIDE + d] = hrel[idx];
        sW[r * RELSTRIDE + d] = wrel[idx];
    }

    // ---- stage KV window (global c-major -> shared pos-major) ----
    const float* kvbase = g_qkv + ((size_t)b * OQKV + 256 + head * 64) * SPATIAL;
    for (int idx = tid; idx < 64 * WINP; idx += 128) {
        const int c = idx / WINP, p = idx % WINP;
        const int y = p / WIN, xx = p % WIN;
        const int gh = by * BLOCK_SZ + y - HALO;
        const int gw = bx * BLOCK_SZ + xx - HALO;
        float v = 0.f;
        if ((unsigned)gh < (unsigned)HW && (unsigned)gw < (unsigned)HW)
            v = kvbase[(size_t)c * SPATIAL + gh * HW + gw];
        sKV[p * KV_STRIDE + c] = v;
    }

    // ---- load Q row as f32x2 d-pairs ----
    const int q    = tid >> 1;
    const int half = tid & 1;
    const int qi = q >> 3, qj = q & 7;
    const int sp = (by * BLOCK_SZ + qi) * HW + bx * BLOCK_SZ + qj;
    const float* qbase = g_qkv + ((size_t)b * OQKV + head * DHEAD) * SPATIAL + sp;

    u64 q2[16];
#pragma unroll
    for (int dd = 0; dd < 16; dd++)
        q2[dd] = pack2(qbase[(size_t)(2 * dd) * SPATIAL], qbase[(size_t)(2 * dd + 1) * SPATIAL]);

    __syncthreads();

    // ---- relative position terms ----
    float rw[14];
#pragma unroll
    for (int xx = 0; xx < 14; xx++) {
        const ulonglong2* wr = (const ulonglong2*)&sW[(13 + xx - qj) * RELSTRIDE];
        u64 s0 = 0ULL, s1 = 0ULL;
#pragma unroll
        for (int m = 0; m < 8; m++) {
            ulonglong2 wv = wr[m];
            fma2(s0, q2[2 * m],     wv.x);
            fma2(s1, q2[2 * m + 1], wv.y);
        }
        float l0, h0; unpack2(add2(s0, s1), l0, h0);
        rw[xx] = l0 + h0;
    }
    const int y0 = half * 7;
    float rh[7];
#pragma unroll
    for (int yy = 0; yy < 7; yy++) {
        const ulonglong2* hr = (const ulonglong2*)&sH[(13 + y0 + yy - qi) * RELSTRIDE];
        u64 s0 = 0ULL, s1 = 0ULL;
#pragma unroll
        for (int m = 0; m < 8; m++) {
            ulonglong2 hv = hr[m];
            fma2(s0, q2[2 * m],     hv.x);
            fma2(s1, q2[2 * m + 1], hv.y);
        }
        float l0, h0; unpack2(add2(s0, s1), l0, h0);
        rh[yy] = l0 + h0;
    }
    // fold QK scale into q
    const u64 sc2 = pack2(SCALE, SCALE);
#pragma unroll
    for (int dd = 0; dd < 16; dd++) mul2(q2[dd], sc2);

    // ---- flash loop over this half's 7 window rows ----
    float m = -1e30f, l = 0.f;
    u64 acc2[16];
#pragma unroll
    for (int dd = 0; dd < 16; dd++) acc2[dd] = 0ULL;

    for (int yy = 0; yy < 7; yy++) {
        const float* kvp = sKV + (y0 + yy) * WIN * KV_STRIDE;
        const float rhv = rh[yy];
        float lg[14];
        float rowm = -1e30f;
#pragma unroll
        for (int xx = 0; xx < 14; xx++) {
            const ulonglong2* kp = (const ulonglong2*)(kvp + xx * KV_STRIDE);
            u64 s0 = 0ULL, s1 = 0ULL;
#pragma unroll
            for (int mm = 0; mm < 8; mm++) {
                ulonglong2 kv = kp[mm];
                fma2(s0, q2[2 * mm],     kv.x);
                fma2(s1, q2[2 * mm + 1], kv.y);
            }
            float l0, h0; unpack2(add2(s0, s1), l0, h0);
            const float s = l0 + h0 + rhv + rw[xx];
            lg[xx] = s;
            rowm = fmaxf(rowm, s);
        }
        const float mnew = fmaxf(m, rowm);
        const float corr = __expf(m - mnew);
        l *= corr;
        const u64 c2 = pack2(corr, corr);
#pragma unroll
        for (int dd = 0; dd < 16; dd++) mul2(acc2[dd], c2);
        m = mnew;
#pragma unroll
        for (int xx = 0; xx < 14; xx++) {
            const float p_ = __expf(lg[xx] - m);
            l += p_;
            const u64 p2 = pack2(p_, p_);
            const ulonglong2* vp = (const ulonglong2*)(kvp + xx * KV_STRIDE + 32);
#pragma unroll
            for (int mm = 0; mm < 8; mm++) {
                ulonglong2 vv = vp[mm];
                fma2(acc2[2 * mm],     p2, vv.x);
                fma2(acc2[2 * mm + 1], p2, vv.y);
            }
        }
    }

    // ---- combine the two halves (adjacent lanes) via shuffle ----
    const unsigned FULL = 0xFFFFFFFFu;
    const float m2 = __shfl_xor_sync(FULL, m, 1);
    const float M  = fmaxf(m, m2);
    const float w  = __expf(m - M);
    const float lw = l * w;
    const float L  = lw + __shfl_xor_sync(FULL, lw, 1);
    const float inv = 1.0f / L;

    float* ob = out + ((size_t)b * 256 + head * DHEAD) * SPATIAL + sp;
#pragma unroll
    for (int dd = 0; dd < 16; dd++) {
        float f0, f1; unpack2(acc2[dd], f0, f1);
        f0 *= w; f1 *= w;
        f0 += __shfl_xor_sync(FULL, f0, 1);
        f1 += __shfl_xor_sync(FULL, f1, 1);
        if (half == 0) {
            ob[(size_t)(2 * dd) * SPATIAL]     = f0 * inv;
            ob[(size_t)(2 * dd + 1) * SPATIAL] = f1 * inv;
        }
    }
}

// ---------------- launch ----------------
extern "C" void kernel_launch(void* const* d_in, const int* in_sizes, int n_in,
                              void* d_out, int out_size)
{
    const float* x    = (const float*)d_in[0];
    const float* qw   = (const float*)d_in[1];
    const float* kvw  = (const float*)d_in[2];
    const float* hrel = (const float*)d_in[3];
    const float* wrel = (const float*)d_in[4];
    float* out = (float*)d_out;

    cudaFuncSetAttribute(halo_attn, cudaFuncAttributeMaxDynamicSharedMemorySize,
                         SMEM_BYTES);

    qkv_gemm<<<dim3(SPATIAL / GBN, OQKV / GBM, BATCH), 256>>>(x, qw, kvw);
    halo_attn<<<dim3(NB, BATCH * NUM_HEADS), 128, SMEM_BYTES>>>(hrel, wrel, out);
}

// round 5
// speedup vs baseline: 1.9417x; 1.0868x over previous
#include <cuda_runtime.h>
#include <cstdint>
#include <cstddef>

// ---------------- problem constants ----------------
#define NUM_HEADS 8
#define DHEAD 32
#define BLOCK_SZ 8
#define HALO 3
#define WIN 14          // BLOCK + 2*HALO
#define WINP 196        // WIN*WIN
#define NHB 12          // 96/8
#define NB 144          // 12*12
#define HW 96
#define SPATIAL 9216    // 96*96
#define BATCH 8
#define CIN 256
#define OQKV 768        // 256 q + 512 kv
#define SCALE 0.17677669529663687f

typedef unsigned long long u64;

// ---- f32x2 packed-math helpers (Blackwell dual-rate fp32) ----
__device__ __forceinline__ u64 pack2(float lo, float hi) {
    u64 r; asm("mov.b64 %0, {%1, %2};" : "=l"(r) : "f"(lo), "f"(hi)); return r;
}
__device__ __forceinline__ void unpack2(u64 v, float& lo, float& hi) {
    asm("mov.b64 {%0, %1}, %2;" : "=f"(lo), "=f"(hi) : "l"(v));
}
__device__ __forceinline__ void fma2(u64& d, u64 a, u64 b) {
    asm("fma.rn.f32x2 %0, %1, %2, %0;" : "+l"(d) : "l"(a), "l"(b));
}
__device__ __forceinline__ void mul2(u64& d, u64 a) {
    asm("mul.rn.f32x2 %0, %0, %1;" : "+l"(d) : "l"(a));
}
__device__ __forceinline__ u64 add2(u64 a, u64 b) {
    u64 r; asm("add.rn.f32x2 %0, %1, %2;" : "=l"(r) : "l"(a), "l"(b)); return r;
}

// scratch: qkv[b][o][s], o<256 -> q (head*32+d), o>=256 -> kv (256 + head*64 + c)
__device__ float g_qkv[(size_t)BATCH * OQKV * SPATIAL];

// ---------------- kernel 1: fused QKV projection GEMM (round-2 version) ----
// tile 128x128, BK=16, 256 threads, 8x8 micro-tile, FFMA2 with B dup packs.
#define GBM 128
#define GBN 128
#define GBK 16
#define APAD 132   // As row stride (words)

__global__ void __launch_bounds__(256, 2) qkv_gemm(
    const float* __restrict__ x,
    const float* __restrict__ qw,
    const float* __restrict__ kvw)
{
    __shared__ float As[GBK][APAD];   // [k][m]
    __shared__ float Bs[GBK][GBN];    // [k][n]

    const int b  = blockIdx.z;
    const int m0 = blockIdx.y * GBM;
    const int n0 = blockIdx.x * GBN;
    const int tid = threadIdx.x;

    const float* xb = x + (size_t)b * CIN * SPATIAL;

    const int tr = tid >> 4;          // 0..15
    const int tc = tid & 15;          // 0..15

    const int a_row0 = tid >> 2;
    const int a_ck   = (tid & 3) * 4;
    const int b_kr0  = tid >> 5;
    const int b_col  = (tid & 31) * 4;

    const float* wrowp[2];
#pragma unroll
    for (int i = 0; i < 2; i++) {
        const int o = m0 + a_row0 + i * 64;
        wrowp[i] = (o < 256) ? (qw + (size_t)o * CIN) : (kvw + (size_t)(o - 256) * CIN);
    }

    u64 acc2[4][8];
#pragma unroll
    for (int i = 0; i < 4; i++)
#pragma unroll
        for (int j = 0; j < 8; j++) acc2[i][j] = 0ULL;

    float4 pa[2], pb[2];
#pragma unroll
    for (int i = 0; i < 2; i++) {
        pa[i] = *(const float4*)(wrowp[i] + 0 + a_ck);
        pb[i] = *(const float4*)(xb + (size_t)(0 + b_kr0 + i * 8) * SPATIAL + n0 + b_col);
    }

    for (int k0 = 0; k0 < CIN; k0 += GBK) {
#pragma unroll
        for (int i = 0; i < 2; i++) {
            const int ar = a_row0 + i * 64;
            As[a_ck + 0][ar] = pa[i].x;
            As[a_ck + 1][ar] = pa[i].y;
            As[a_ck + 2][ar] = pa[i].z;
            As[a_ck + 3][ar] = pa[i].w;
            *(float4*)&Bs[b_kr0 + i * 8][b_col] = pb[i];
        }
        __syncthreads();

        if (k0 + GBK < CIN) {
#pragma unroll
            for (int i = 0; i < 2; i++) {
                pa[i] = *(const float4*)(wrowp[i] + k0 + GBK + a_ck);
                pb[i] = *(const float4*)(xb + (size_t)(k0 + GBK + b_kr0 + i * 8) * SPATIAL + n0 + b_col);
            }
        }

#pragma unroll
        for (int k = 0; k < GBK; k++) {
            ulonglong2 a01 = *(const ulonglong2*)&As[k][tr * 8];
            ulonglong2 a23 = *(const ulonglong2*)&As[k][tr * 8 + 4];
            u64 a2[4] = {a01.x, a01.y, a23.x, a23.y};
            float4 b0 = *(const float4*)&Bs[k][tc * 8];
            float4 b1 = *(const float4*)&Bs[k][tc * 8 + 4];
            u64 bd[8];
            bd[0] = pack2(b0.x, b0.x); bd[1] = pack2(b0.y, b0.y);
            bd[2] = pack2(b0.z, b0.z); bd[3] = pack2(b0.w, b0.w);
            bd[4] = pack2(b1.x, b1.x); bd[5] = pack2(b1.y, b1.y);
            bd[6] = pack2(b1.z, b1.z); bd[7] = pack2(b1.w, b1.w);
#pragma unroll
            for (int i = 0; i < 4; i++)
#pragma unroll
                for (int j = 0; j < 8; j++)
                    fma2(acc2[i][j], a2[i], bd[j]);
        }
        __syncthreads();
    }

    float* outb = g_qkv + (size_t)b * OQKV * SPATIAL;
#pragma unroll
    for (int i = 0; i < 4; i++) {
        float lo[8], hi[8];
#pragma unroll
        for (int j = 0; j < 8; j++) unpack2(acc2[i][j], lo[j], hi[j]);
        const int r0 = m0 + tr * 8 + 2 * i;
        float* p0 = outb + (size_t)r0 * SPATIAL + n0 + tc * 8;
        float* p1 = p0 + SPATIAL;
        *(float4*)(p0)     = make_float4(lo[0], lo[1], lo[2], lo[3]);
        *(float4*)(p0 + 4) = make_float4(lo[4], lo[5], lo[6], lo[7]);
        *(float4*)(p1)     = make_float4(hi[0], hi[1], hi[2], hi[3]);
        *(float4*)(p1 + 4) = make_float4(hi[4], hi[5], hi[6], hi[7]);
    }
}

// ---------------- kernel 2: halo attention ----------------
// Round-4 structure; softmax inner restructured: tree max, batched MUFU exp,
// tree sum, then dense AV fma2 stream.
#define KV_STRIDE 68                         // 64 ch + pad
#define SMEM_KV   (WINP * KV_STRIDE)         // 13328 floats
#define RELSTRIDE 36
#define SMEM_REL  (27 * RELSTRIDE)
#define SMEM_FLOATS (SMEM_KV + 2 * SMEM_REL)
#define SMEM_BYTES  (SMEM_FLOATS * 4)

__global__ void __launch_bounds__(128) halo_attn(
    const float* __restrict__ hrel,
    const float* __restrict__ wrel,
    float* __restrict__ out)
{
    extern __shared__ float smem[];
    float* sKV = smem;                       // [196][68] : c<32 K, c>=32 V
    float* sH  = smem + SMEM_KV;             // [27][36]
    float* sW  = sH + SMEM_REL;              // [27][36]

    const int tid = threadIdx.x;
    const int nbidx = blockIdx.x;            // 0..143
    const int bh = blockIdx.y;               // 0..63
    const int b = bh >> 3, head = bh & 7;
    const int by = nbidx / NHB, bx = nbidx % NHB;

    // ---- stage rel tables ----
    for (int idx = tid; idx < 27 * 32; idx += 128) {
        const int r = idx >> 5, d = idx & 31;
        sH[r * RELSTRIDE + d] = hrel[idx];
        sW[r * RELSTRIDE + d] = wrel[idx];
    }

    // ---- stage KV window ----
    const float* kvbase = g_qkv + ((size_t)b * OQKV + 256 + head * 64) * SPATIAL;
    for (int idx = tid; idx < 64 * WINP; idx += 128) {
        const int c = idx / WINP, p = idx % WINP;
        const int y = p / WIN, xx = p % WIN;
        const int gh = by * BLOCK_SZ + y - HALO;
        const int gw = bx * BLOCK_SZ + xx - HALO;
        float v = 0.f;
        if ((unsigned)gh < (unsigned)HW && (unsigned)gw < (unsigned)HW)
            v = kvbase[(size_t)c * SPATIAL + gh * HW + gw];
        sKV[p * KV_STRIDE + c] = v;
    }

    // ---- load Q row as f32x2 d-pairs ----
    const int q    = tid >> 1;
    const int half = tid & 1;
    const int qi = q >> 3, qj = q & 7;
    const int sp = (by * BLOCK_SZ + qi) * HW + bx * BLOCK_SZ + qj;
    const float* qbase = g_qkv + ((size_t)b * OQKV + head * DHEAD) * SPATIAL + sp;

    u64 q2[16];
#pragma unroll
    for (int dd = 0; dd < 16; dd++)
        q2[dd] = pack2(qbase[(size_t)(2 * dd) * SPATIAL], qbase[(size_t)(2 * dd + 1) * SPATIAL]);

    __syncthreads();

    // ---- relative position terms ----
    float rw[14];
#pragma unroll
    for (int xx = 0; xx < 14; xx++) {
        const ulonglong2* wr = (const ulonglong2*)&sW[(13 + xx - qj) * RELSTRIDE];
        u64 s0 = 0ULL, s1 = 0ULL;
#pragma unroll
        for (int m = 0; m < 8; m++) {
            ulonglong2 wv = wr[m];
            fma2(s0, q2[2 * m],     wv.x);
            fma2(s1, q2[2 * m + 1], wv.y);
        }
        float l0, h0; unpack2(add2(s0, s1), l0, h0);
        rw[xx] = l0 + h0;
    }
    const int y0 = half * 7;
    float rh[7];
#pragma unroll
    for (int yy = 0; yy < 7; yy++) {
        const ulonglong2* hr = (const ulonglong2*)&sH[(13 + y0 + yy - qi) * RELSTRIDE];
        u64 s0 = 0ULL, s1 = 0ULL;
#pragma unroll
        for (int m = 0; m < 8; m++) {
            ulonglong2 hv = hr[m];
            fma2(s0, q2[2 * m],     hv.x);
            fma2(s1, q2[2 * m + 1], hv.y);
        }
        float l0, h0; unpack2(add2(s0, s1), l0, h0);
        rh[yy] = l0 + h0;
    }
    const u64 sc2 = pack2(SCALE, SCALE);
#pragma unroll
    for (int dd = 0; dd < 16; dd++) mul2(q2[dd], sc2);

    // ---- flash loop over this half's 7 window rows ----
    float m = -1e30f, l = 0.f;
    u64 acc2[16];
#pragma unroll
    for (int dd = 0; dd < 16; dd++) acc2[dd] = 0ULL;

    for (int yy = 0; yy < 7; yy++) {
        const float* kvp = sKV + (y0 + yy) * WIN * KV_STRIDE;
        const float rhv = rh[yy];
        float lg[14];
#pragma unroll
        for (int xx = 0; xx < 14; xx++) {
            const ulonglong2* kp = (const ulonglong2*)(kvp + xx * KV_STRIDE);
            u64 s0 = 0ULL, s1 = 0ULL;
#pragma unroll
            for (int mm = 0; mm < 8; mm++) {
                ulonglong2 kv = kp[mm];
                fma2(s0, q2[2 * mm],     kv.x);
                fma2(s1, q2[2 * mm + 1], kv.y);
            }
            float l0, h0; unpack2(add2(s0, s1), l0, h0);
            lg[xx] = l0 + h0 + rhv + rw[xx];
        }
        // tree max (depth 4)
        float t0 = fmaxf(lg[0], lg[1]),  t1 = fmaxf(lg[2], lg[3]);
        float t2 = fmaxf(lg[4], lg[5]),  t3 = fmaxf(lg[6], lg[7]);
        float t4 = fmaxf(lg[8], lg[9]),  t5 = fmaxf(lg[10], lg[11]);
        float t6 = fmaxf(lg[12], lg[13]);
        t0 = fmaxf(t0, t1); t2 = fmaxf(t2, t3); t4 = fmaxf(t4, t5);
        const float rowm = fmaxf(fmaxf(t0, t2), fmaxf(t4, t6));

        const float mnew = fmaxf(m, rowm);
        const float corr = __expf(m - mnew);
        m = mnew;

        // batched independent exps (MUFU pipelines)
#pragma unroll
        for (int xx = 0; xx < 14; xx++) lg[xx] = __expf(lg[xx] - mnew);

        // tree sum of p's + l rescale
        float u0 = lg[0] + lg[1],   u1 = lg[2] + lg[3];
        float u2 = lg[4] + lg[5],   u3 = lg[6] + lg[7];
        float u4 = lg[8] + lg[9],   u5 = lg[10] + lg[11];
        float u6 = lg[12] + lg[13];
        l = l * corr + ((u0 + u1) + (u2 + u3)) + ((u4 + u5) + u6);

        // rescale acc
        const u64 c2 = pack2(corr, corr);
#pragma unroll
        for (int dd = 0; dd < 16; dd++) mul2(acc2[dd], c2);

        // dense AV stream (all multipliers ready)
#pragma unroll
        for (int xx = 0; xx < 14; xx++) {
            const u64 p2 = pack2(lg[xx], lg[xx]);
            const ulonglong2* vp = (const ulonglong2*)(kvp + xx * KV_STRIDE + 32);
#pragma unroll
            for (int mm = 0; mm < 8; mm++) {
                ulonglong2 vv = vp[mm];
                fma2(acc2[2 * mm],     p2, vv.x);
                fma2(acc2[2 * mm + 1], p2, vv.y);
            }
        }
    }

    // ---- combine the two halves (adjacent lanes) via shuffle ----
    const unsigned FULL = 0xFFFFFFFFu;
    const float m2 = __shfl_xor_sync(FULL, m, 1);
    const float M  = fmaxf(m, m2);
    const float w  = __expf(m - M);
    const float lw = l * w;
    const float L  = lw + __shfl_xor_sync(FULL, lw, 1);
    const float inv = 1.0f / L;

    float* ob = out + ((size_t)b * 256 + head * DHEAD) * SPATIAL + sp;
#pragma unroll
    for (int dd = 0; dd < 16; dd++) {
        float f0, f1; unpack2(acc2[dd], f0, f1);
        f0 *= w; f1 *= w;
        f0 += __shfl_xor_sync(FULL, f0, 1);
        f1 += __shfl_xor_sync(FULL, f1, 1);
        if (half == 0) {
            ob[(size_t)(2 * dd) * SPATIAL]     = f0 * inv;
            ob[(size_t)(2 * dd + 1) * SPATIAL] = f1 * inv;
        }
    }
}

// ---------------- launch ----------------
extern "C" void kernel_launch(void* const* d_in, const int* in_sizes, int n_in,
                              void* d_out, int out_size)
{
    const float* x    = (const float*)d_in[0];
    const float* qw   = (const float*)d_in[1];
    const float* kvw  = (const float*)d_in[2];
    const float* hrel = (const float*)d_in[3];
    const float* wrel = (const float*)d_in[4];
    float* out = (float*)d_out;

    cudaFuncSetAttribute(halo_attn, cudaFuncAttributeMaxDynamicSharedMemorySize,
                         SMEM_BYTES);

    qkv_gemm<<<dim3(SPATIAL / GBN, OQKV / GBM, BATCH), 256>>>(x, qw, kvw);
    halo_attn<<<dim3(NB, BATCH * NUM_HEADS), 128, SMEM_BYTES>>>(hrel, wrel, out);
}